// round 7
// baseline (speedup 1.0000x reference)
#include <cuda_runtime.h>

#define NN   100000
#define INC  128
#define HID  16
#define OUTC 64

// Scratch (allocation-free rule: __device__ globals)
__device__ __align__(16) int   g_deg_i[NN];
__device__ __align__(16) float g_dinv[NN];
__device__ __align__(16) float g_h[NN * HID];    // h1, then relu(h)
__device__ __align__(16) float g_agg[NN * HID];  // agg1, then agg2

__global__ void k_init_deg() {
    int i = blockIdx.x * blockDim.x + threadIdx.x;
    if (i < NN) g_deg_i[i] = 1;  // self loop contributes 1
}

__global__ void k_count(const int* __restrict__ col, int E) {
    int e = blockIdx.x * blockDim.x + threadIdx.x;
    if (e < E) atomicAdd(&g_deg_i[col[e]], 1);  // integer RED.ADD
}

__global__ void k_dinv() {
    int i = blockIdx.x * blockDim.x + threadIdx.x;
    if (i < NN) g_dinv[i] = rsqrtf((float)g_deg_i[i]);  // deg >= 1 always
}

// h = X @ W1 ; agg = h * dinv^2 (self-loop init). 16 rows per 256-thread block.
__global__ void k_gemm1(const float* __restrict__ x, const float* __restrict__ W1) {
    __shared__ float xs[16 * 128];
    __shared__ float ws[128 * 16];
    int r0 = blockIdx.x * 16;
    int t = threadIdx.x;
    for (int i = t; i < 16 * 128; i += 256) {
        xs[i] = x[r0 * 128 + i];
        ws[i] = W1[i];
    }
    __syncthreads();
    int r = t >> 4, c = t & 15;
    float acc = 0.0f;
#pragma unroll
    for (int k = 0; k < 128; k++)
        acc = fmaf(xs[r * 128 + k], ws[k * 16 + c], acc);
    float di = g_dinv[r0 + r];
    int idx = (r0 + r) * HID + c;
    g_h[idx] = acc;
    g_agg[idx] = acc * di * di;
}

// 4 threads per edge; thread j owns columns {j, j+4, j+8, j+12}.
// Per-thread atomic addresses are 16B apart -> no vector fusion possible;
// across the 4-lane quad each atomic instruction covers 16 contiguous bytes.
__global__ void k_edge(const int* __restrict__ row,
                       const int* __restrict__ col, int E) {
    unsigned gid = blockIdx.x * blockDim.x + threadIdx.x;
    int e = gid >> 2;
    int j = gid & 3;
    if (e >= E) return;
    int r = row[e];
    int c = col[e];
    float nrm = g_dinv[r] * g_dinv[c];
    const float* hp = g_h + r * HID;
    float* ap = g_agg + c * HID;
#pragma unroll
    for (int i = 0; i < 4; i++) {
        int k = j + 4 * i;
        atomicAdd(ap + k, hp[k] * nrm);
    }
}

// h = relu(agg1 + b1) ; agg2 = h * dinv^2 (self-loop init for layer 2, in place)
__global__ void k_relu(const float* __restrict__ b1) {
    int idx = blockIdx.x * blockDim.x + threadIdx.x;
    if (idx >= NN * HID) return;
    int i = idx >> 4;
    int c = idx & 15;
    float v = g_agg[idx] + b1[c];
    v = v > 0.0f ? v : 0.0f;
    float di = g_dinv[i];
    g_h[idx] = v;
    g_agg[idx] = v * di * di;
}

// out = agg2 @ W2 + b2. 4 rows per 256-thread block.
__global__ void k_gemm2(const float* __restrict__ W2, const float* __restrict__ b2,
                        float* __restrict__ out) {
    __shared__ float as[4 * 16];
    __shared__ float ws[16 * 64];
    int r0 = blockIdx.x * 4;
    int t = threadIdx.x;
    if (t < 64) as[t] = g_agg[r0 * HID + t];
    for (int i = t; i < 16 * 64; i += 256) ws[i] = W2[i];
    __syncthreads();
    int r = t >> 6, c = t & 63;
    float acc = b2[c];
#pragma unroll
    for (int k = 0; k < 16; k++)
        acc = fmaf(as[r * 16 + k], ws[k * 64 + c], acc);
    out[(r0 + r) * OUTC + c] = acc;
}

extern "C" void kernel_launch(void* const* d_in, const int* in_sizes, int n_in,
                              void* d_out, int out_size) {
    const float* x   = (const float*)d_in[0];
    const int*   ei  = (const int*)d_in[1];   // JAX silently downcast int64->int32
    const float* W1  = (const float*)d_in[2];
    const float* b1  = (const float*)d_in[3];
    const float* W2  = (const float*)d_in[4];
    const float* b2  = (const float*)d_in[5];
    float*       out = (float*)d_out;

    int E = in_sizes[1] / 2;
    const int* row = ei;       // sources
    const int* col = ei + E;   // targets

    k_init_deg<<<(NN + 255) / 256, 256>>>();
    k_count<<<(E + 255) / 256, 256>>>(col, E);
    k_dinv<<<(NN + 255) / 256, 256>>>();
    k_gemm1<<<NN / 16, 256>>>(x, W1);
    k_edge<<<(4 * E + 255) / 256, 256>>>(row, col, E);
    k_relu<<<(NN * HID + 255) / 256, 256>>>(b1);
    k_edge<<<(4 * E + 255) / 256, 256>>>(row, col, E);
    k_gemm2<<<NN / 4, 256>>>(W2, b2, out);
}